// round 15
// baseline (speedup 1.0000x reference)
#include <cuda_runtime.h>
#include <cuda_bf16.h>
#include <cstdint>

#define BB 256
#define SS 1024
#define DD 64
#define HD 128
#define FF 40

// ---------------- smem layout (byte offsets) ----------------
// bf16 rows of 64 K-elements padded to 144 bytes (conflict-free frag loads)
#define WSTR 144
#define OFF_WHI 0                  // 128 n x 144
#define OFF_WLO 18432
#define OFF_EHI 36864              // 80 n x 144 (Weff^T, 2 heads x 40)
#define OFF_ELO 48384
#define OFF_XHI 59904              // 64 rows x 144
#define OFF_XLO 69120
#define OFF_BX  78336              // 128 f32
#define OFF_C   78848              // 80 f32
#define OFF_W2  79168              // 40 f32
#define OFF_SQ  79328              // 128 f32 ([jh][64 rows])
#define OFF_RED 79840              // 8w x 4tig x 16 f32 = 2048
#define SMEM_TOTAL 81920

// ---------------- helpers ----------------
__device__ __forceinline__ float prelu_f(float x, float a) { return x >= 0.0f ? x : a * x; }
__device__ __forceinline__ float bfl(uint32_t u) { return __uint_as_float(u << 16); }
__device__ __forceinline__ float bfh(uint32_t u) { return __uint_as_float(u & 0xffff0000u); }

__device__ __forceinline__ uint32_t smem_u32(const void* p) {
    uint32_t a;
    asm("{ .reg .u64 t; cvta.to.shared.u64 t, %1; cvt.u32.u64 %0, t; }" : "=r"(a) : "l"(p));
    return a;
}

// pack (f0 -> low half, f1 -> high half)
__device__ __forceinline__ uint32_t pkbf(float f0, float f1) {
    uint32_t r;
    asm("cvt.rn.bf16x2.f32 %0, %1, %2;" : "=r"(r) : "f"(f1), "f"(f0));
    return r;
}
// split pair into bf16 hi + bf16 residual lo
__device__ __forceinline__ void split2(float f0, float f1, uint32_t& hi, uint32_t& lo) {
    uint32_t h = pkbf(f0, f1);
    lo = pkbf(f0 - bfl(h), f1 - bfh(h));
    hi = h;
}

__device__ __forceinline__ void mma_bf16(float* c, const uint32_t* a, const uint32_t* b) {
    asm volatile(
        "mma.sync.aligned.m16n8k16.row.col.f32.bf16.bf16.f32 "
        "{%0,%1,%2,%3}, {%4,%5,%6,%7}, {%8,%9}, {%0,%1,%2,%3};"
        : "+f"(c[0]), "+f"(c[1]), "+f"(c[2]), "+f"(c[3])
        : "r"(a[0]), "r"(a[1]), "r"(a[2]), "r"(a[3]), "r"(b[0]), "r"(b[1]));
}

__device__ __forceinline__ void ldsm4(uint32_t* r, uint32_t addr) {
    asm volatile("ldmatrix.sync.aligned.m8n8.x4.shared.b16 {%0,%1,%2,%3}, [%4];"
        : "=r"(r[0]), "=r"(r[1]), "=r"(r[2]), "=r"(r[3]) : "r"(addr));
}
__device__ __forceinline__ void ldsm2(uint32_t* r, uint32_t addr) {
    asm volatile("ldmatrix.sync.aligned.m8n8.x2.shared.b16 {%0,%1}, [%2];"
        : "=r"(r[0]), "=r"(r[1]) : "r"(addr));
}

// ---------------- device scratch ----------------
// pre-split transposed bf16 weights (written by k_pre, copied by k_main)
__device__ float4 g_wxs[2][2][1024];        // [br][hi/lo][128 rows x 64 d bf16]
__device__ float4 g_weffs_hi[2 * BB][640];  // [(br*BB+b)][80 rows x 64 d bf16]
__device__ float4 g_weffs_lo[2 * BB][640];
__device__ float g_c[2 * BB * 2 * FF];
__device__ float g_part[4][2 * BB * HD];

// ============ kernel 1: y_trans + split W_eff + c, one (b, br, h) per block ============
// w1 rows 0..255 staged into smem COALESCED; compute loops read smem.
__global__ __launch_bounds__(256) void k_pre(
    const float* __restrict__ y, const float* __restrict__ w_ty,
    const float* __restrict__ b_ty, const float* __restrict__ a_ty,
    const float* __restrict__ uid, const float* __restrict__ osb,
    const float* __restrict__ zip,
    const float* __restrict__ lw1, const float* __restrict__ lb1,
    const float* __restrict__ nw1, const float* __restrict__ nb1,
    const float* __restrict__ wlx, const float* __restrict__ wnx) {
    int b = blockIdx.x, br = blockIdx.y, h = blockIdx.z, t = threadIdx.x;
    const float* w1 = br ? nw1 : lw1;
    const float* b1 = br ? nb1 : lb1;
    __shared__ float ys[DD], yt[HD], side[56], red[4];
    __shared__ float sw1[256 * FF];   // 40 KB: w1 rows 0..255

    // coalesced stage of w1 rows 0..255
    for (int i = t; i < 256 * FF; i += 256) sw1[i] = w1[i];

    if (t < DD) ys[t] = y[b * DD + t];
    else if (t >= 64 && t < 120) {
        int k = t - 64;
        side[k] = (k < 32) ? uid[b * 32 + k]
                : (k < 40) ? osb[b * 8 + (k - 32)]
                           : zip[b * 16 + (k - 40)];
    }
    __syncthreads();
    float tv = 0.0f;
    if (t < HD) {
        float acc = b_ty[t];
#pragma unroll
        for (int d = 0; d < DD; d++) acc = fmaf(ys[d], w_ty[d * HD + t], acc);
        tv = prelu_f(acc, a_ty[0]);
        float sq = tv * tv;
#pragma unroll
        for (int off = 16; off; off >>= 1) sq += __shfl_xor_sync(~0u, sq, off);
        if ((t & 31) == 0) red[t >> 5] = sq;
    }
    __syncthreads();
    if (t < HD) {
        float s = red[0] + red[1] + red[2] + red[3];
        yt[t] = tv * (1.0f / fmaxf(sqrtf(s), 1e-12f));
    }
    __syncthreads();

    // W_eff rows h*40..h*40+39, split + transposed [f][d], coalesced stores
    {
        __nv_bfloat16* ehi = (__nv_bfloat16*)g_weffs_hi[br * BB + b] + h * 40 * 64;
        __nv_bfloat16* elo = (__nv_bfloat16*)g_weffs_lo[br * BB + b] + h * 40 * 64;
        for (int i = t; i < 40 * 64; i += 256) {
            int f = i >> 6, d = i & 63;
            float v = sw1[d * FF + f] + sw1[(128 + d) * FF + f]
                    + yt[h * DD + d] * sw1[(64 + d) * FF + f];
            __nv_bfloat16 hv = __float2bfloat16(v);
            ehi[i] = hv;
            elo[i] = __float2bfloat16(v - __bfloat162float(hv));
        }
    }
    // c vector for this head (rows 128..255 from smem; side rows 256..311 from gmem)
    if (t < FF) {
        float acc = b1[t];
#pragma unroll 8
        for (int d = 0; d < DD; d++)
            acc += yt[h * DD + d] * (sw1[(192 + d) * FF + t] - sw1[(128 + d) * FF + t]);
#pragma unroll 8
        for (int k = 0; k < 56; k++) acc += side[k] * w1[(256 + k) * FF + t];
        g_c[(((size_t)br * BB + b) * 2 + h) * FF + t] = acc;
    }
    // wx split (once per branch)
    if (b == 0 && h == 0) {
        const float* wx = br ? wnx : wlx;
        __nv_bfloat16* whi = (__nv_bfloat16*)g_wxs[br][0];
        __nv_bfloat16* wlo = (__nv_bfloat16*)g_wxs[br][1];
        for (int i = t; i < DD * HD; i += 256) {
            int j = i >> 6, d = i & 63;
            float v = wx[d * HD + j];
            __nv_bfloat16 hv = __float2bfloat16(v);
            whi[i] = hv;
            wlo[i] = __float2bfloat16(v - __bfloat162float(hv));
        }
    }
}

// ============ kernel 2: main mma.sync kernel (copy-only setup; 2 barriers/tile) ============
__global__ __launch_bounds__(256, 2) void k_main(
    const float* __restrict__ xl, const float* __restrict__ xn_g,
    const float* __restrict__ blx, const float* __restrict__ alx,
    const float* __restrict__ bnx, const float* __restrict__ anx,
    const float* __restrict__ la1, const float* __restrict__ na1,
    const float* __restrict__ lw2, const float* __restrict__ lb2,
    const float* __restrict__ nw2, const float* __restrict__ nb2) {
    extern __shared__ char sm[];
    const uint32_t sb = smem_u32(sm);
    const int b = blockIdx.x, br = blockIdx.y, sh = blockIdx.z;
    const int t = threadIdx.x;
    const int w = t >> 5, lane = t & 31;
    const int mw = w & 3, jh = w >> 2;   // m-warp (rows mw*16..), n-half / head
    const int g = lane >> 2, tig = lane & 3;

    const float* xg = br ? xn_g : xl;
    const float* bx = br ? bnx : blx;
    const float ax = br ? anx[0] : alx[0];
    const float a1 = br ? na1[0] : la1[0];
    const float* w2g = br ? nw2 : lw2;
    const float b2 = br ? nb2[0] : lb2[0];

    float* bxs  = (float*)(sm + OFF_BX);
    float* c_s  = (float*)(sm + OFF_C);
    float* w2_s = (float*)(sm + OFF_W2);
    float* sqf  = (float*)(sm + OFF_SQ);
    float* redf = (float*)(sm + OFF_RED);

    // per-lane ldmatrix address components
    const uint32_t a_off = (uint32_t)(lane & 15) * WSTR + (uint32_t)(lane >> 4) * 16;
    const uint32_t b_off = (uint32_t)((lane >> 4) * 8 + (lane & 7)) * WSTR
                         + (uint32_t)((lane >> 3) & 1) * 16;
    const uint32_t b2_off = (uint32_t)(lane & 7) * WSTR + (uint32_t)((lane >> 3) & 1) * 16;

    // ---- setup: straight float4 copies of pre-split weights ----
    {
        const float4* swhi = g_wxs[br][0];
        const float4* swlo = g_wxs[br][1];
#pragma unroll
        for (int k = 0; k < 4; k++) {
            int i = t + k * 256;            // 1024 float4 = 128 rows x 8
            int row = i >> 3, q = i & 7;
            *(float4*)(sm + OFF_WHI + row * WSTR + q * 16) = swhi[i];
            *(float4*)(sm + OFF_WLO + row * WSTR + q * 16) = swlo[i];
        }
        const float4* sehi = g_weffs_hi[br * BB + b];
        const float4* selo = g_weffs_lo[br * BB + b];
        for (int i = t; i < 640; i += 256) {  // 80 rows x 8
            int row = i >> 3, q = i & 7;
            *(float4*)(sm + OFF_EHI + row * WSTR + q * 16) = sehi[i];
            *(float4*)(sm + OFF_ELO + row * WSTR + q * 16) = selo[i];
        }
        const float* csrc = g_c + ((size_t)br * BB + b) * 2 * FF;
        if (t < 128) bxs[t] = bx[t];
        else if (t < 208) c_s[t - 128] = csrc[t - 128];
        else if (t < 248) w2_s[t - 208] = w2g[t - 208];
    }

    float racc[16];
#pragma unroll
    for (int i = 0; i < 16; i++) racc[i] = 0.0f;

    // prefetch tile 0
    const float4* xbase = (const float4*)xg + (size_t)(b * SS + sh * 256) * (DD / 4);
    float4 pf[4];
#pragma unroll
    for (int i = 0; i < 4; i++) pf[i] = xbase[t + i * 256];

    __syncthreads();

    for (int tile = 0; tile < 4; ++tile) {
        // ---- store prefetched x tile [64][64] -> split hi/lo bf16 smem ----
#pragma unroll
        for (int i = 0; i < 4; i++) {
            int idx = t + i * 256;          // 1024 float4
            int r = idx >> 4, kq = idx & 15;
            float4 v = pf[i];
            uint32_t h01, l01, h23, l23;
            split2(v.x, v.y, h01, l01);
            split2(v.z, v.w, h23, l23);
            *(uint2*)(sm + OFF_XHI + r * WSTR + kq * 8) = make_uint2(h01, h23);
            *(uint2*)(sm + OFF_XLO + r * WSTR + kq * 8) = make_uint2(l01, l23);
        }
        __syncthreads();   // barrier 1: X tile visible

        // prefetch next tile (LDG latency overlaps stage-1 MMAs)
        if (tile < 3) {
            const float4* xp = xbase + (tile + 1) * 1024;
#pragma unroll
            for (int i = 0; i < 4; i++) pf[i] = xp[t + i * 256];
        }

        // ---- stage 1: t1 = x @ wx (64x128, K=64), 3x bf16 ----
        float acc[8][4];
#pragma unroll
        for (int nt = 0; nt < 8; nt++)
#pragma unroll
            for (int i = 0; i < 4; i++) acc[nt][i] = 0.0f;

#pragma unroll
        for (int kk = 0; kk < 4; kk++) {
            uint32_t aH[4], aL[4];
            uint32_t abase = sb + OFF_XHI + (uint32_t)(mw * 16) * WSTR + kk * 32 + a_off;
            ldsm4(aH, abase);
            ldsm4(aL, abase + (OFF_XLO - OFF_XHI));
#pragma unroll
            for (int np = 0; np < 4; np++) {
                uint32_t bH[4], bL[4];
                uint32_t bbase = sb + OFF_WHI + (uint32_t)(jh * 64 + np * 16) * WSTR + kk * 32 + b_off;
                ldsm4(bH, bbase);
                ldsm4(bL, bbase + (OFF_WLO - OFF_WHI));
                mma_bf16(acc[2 * np], aH, bH);
                mma_bf16(acc[2 * np], aL, bH);
                mma_bf16(acc[2 * np], aH, bL);
                mma_bf16(acc[2 * np + 1], aH, bH + 2);
                mma_bf16(acc[2 * np + 1], aL, bH + 2);
                mma_bf16(acc[2 * np + 1], aH, bL + 2);
            }
        }

        // ---- epilogue 1: bias + prelu + l2norm (in registers, acc reused) ----
        float s0r = 0.0f, s1r = 0.0f;
#pragma unroll
        for (int nt = 0; nt < 8; nt++) {
            int c0 = jh * 64 + nt * 8 + 2 * tig;
            float b0v = bxs[c0], b1v = bxs[c0 + 1];
            float t0 = prelu_f(acc[nt][0] + b0v, ax);
            float t1 = prelu_f(acc[nt][1] + b1v, ax);
            float t2 = prelu_f(acc[nt][2] + b0v, ax);
            float t3 = prelu_f(acc[nt][3] + b1v, ax);
            acc[nt][0] = t0; acc[nt][1] = t1; acc[nt][2] = t2; acc[nt][3] = t3;
            s0r += t0 * t0 + t1 * t1;
            s1r += t2 * t2 + t3 * t3;
        }
        s0r += __shfl_xor_sync(~0u, s0r, 1); s0r += __shfl_xor_sync(~0u, s0r, 2);
        s1r += __shfl_xor_sync(~0u, s1r, 1); s1r += __shfl_xor_sync(~0u, s1r, 2);
        int row0 = mw * 16 + g;
        if (tig == 0) {
            sqf[jh * 64 + row0] = s0r;
            sqf[jh * 64 + row0 + 8] = s1r;
        }
        __syncthreads();   // barrier 2: row sumsq halves visible
        float inv0 = 1.0f / fmaxf(sqrtf(sqf[row0] + sqf[64 + row0]), 1e-12f);
        float inv1 = 1.0f / fmaxf(sqrtf(sqf[row0 + 8] + sqf[64 + row0 + 8]), 1e-12f);

        // normalize + build stage-2 A fragments (register resident)
        uint32_t a2h[4][4], a2l[4][4];
#pragma unroll
        for (int kk = 0; kk < 4; kk++) {
            split2(acc[2 * kk][0] * inv0,     acc[2 * kk][1] * inv0,     a2h[kk][0], a2l[kk][0]);
            split2(acc[2 * kk][2] * inv1,     acc[2 * kk][3] * inv1,     a2h[kk][1], a2l[kk][1]);
            split2(acc[2 * kk + 1][0] * inv0, acc[2 * kk + 1][1] * inv0, a2h[kk][2], a2l[kk][2]);
            split2(acc[2 * kk + 1][2] * inv1, acc[2 * kk + 1][3] * inv1, a2h[kk][3], a2l[kk][3]);
        }

        // ---- stage 2: h1 = xn_h @ Weff_h (64x40, K=64), 3x bf16 ----
        float acc2[5][4];
#pragma unroll
        for (int nt = 0; nt < 5; nt++)
#pragma unroll
            for (int i = 0; i < 4; i++) acc2[nt][i] = 0.0f;
#pragma unroll
        for (int kk = 0; kk < 4; kk++) {
#pragma unroll
            for (int np = 0; np < 2; np++) {
                uint32_t bH[4], bL[4];
                uint32_t bbase = sb + OFF_EHI + (uint32_t)(jh * 40 + np * 16) * WSTR + kk * 32 + b_off;
                ldsm4(bH, bbase);
                ldsm4(bL, bbase + (OFF_ELO - OFF_EHI));
                mma_bf16(acc2[2 * np], a2h[kk], bH);
                mma_bf16(acc2[2 * np], a2l[kk], bH);
                mma_bf16(acc2[2 * np], a2h[kk], bL);
                mma_bf16(acc2[2 * np + 1], a2h[kk], bH + 2);
                mma_bf16(acc2[2 * np + 1], a2l[kk], bH + 2);
                mma_bf16(acc2[2 * np + 1], a2h[kk], bL + 2);
            }
            {
                uint32_t bH[2], bL[2];
                uint32_t bbase = sb + OFF_EHI + (uint32_t)(jh * 40 + 32) * WSTR + kk * 32 + b2_off;
                ldsm2(bH, bbase);
                ldsm2(bL, bbase + (OFF_ELO - OFF_EHI));
                mma_bf16(acc2[4], a2h[kk], bH);
                mma_bf16(acc2[4], a2l[kk], bH);
                mma_bf16(acc2[4], a2h[kk], bL);
            }
        }

        // ---- epilogue 2: p = b2 + sum_f prelu(h1 + c) * w2 ----
        float p0 = 0.0f, p1 = 0.0f;
#pragma unroll
        for (int nt = 0; nt < 5; nt++) {
            int f0 = nt * 8 + 2 * tig;
            float c0v = c_s[jh * 40 + f0], c1v = c_s[jh * 40 + f0 + 1];
            float w0v = w2_s[f0], w1v = w2_s[f0 + 1];
            p0 += prelu_f(acc2[nt][0] + c0v, a1) * w0v + prelu_f(acc2[nt][1] + c1v, a1) * w1v;
            p1 += prelu_f(acc2[nt][2] + c0v, a1) * w0v + prelu_f(acc2[nt][3] + c1v, a1) * w1v;
        }
        p0 += __shfl_xor_sync(~0u, p0, 1); p0 += __shfl_xor_sync(~0u, p0, 2);
        p1 += __shfl_xor_sync(~0u, p1, 1); p1 += __shfl_xor_sync(~0u, p1, 2);
        p0 += b2; p1 += b2;

        // ---- epilogue 3: racc[col] += p0*xn[row g][col] + p1*xn[row g+8][col] ----
        // (register-only; no barrier needed before next tile's X store — no warp
        //  reads XHI/XLO or sqf after barrier 2, and writers of both are gated
        //  behind next tile's barrier 1.)
#pragma unroll
        for (int kk = 0; kk < 4; kk++) {
            float xa0 = bfl(a2h[kk][0]) + bfl(a2l[kk][0]);
            float xa1 = bfh(a2h[kk][0]) + bfh(a2l[kk][0]);
            float xb0 = bfl(a2h[kk][1]) + bfl(a2l[kk][1]);
            float xb1 = bfh(a2h[kk][1]) + bfh(a2l[kk][1]);
            racc[4 * kk + 0] += p0 * xa0 + p1 * xb0;
            racc[4 * kk + 1] += p0 * xa1 + p1 * xb1;
            float ya0 = bfl(a2h[kk][2]) + bfl(a2l[kk][2]);
            float ya1 = bfh(a2h[kk][2]) + bfh(a2l[kk][2]);
            float yb0 = bfl(a2h[kk][3]) + bfl(a2l[kk][3]);
            float yb1 = bfh(a2h[kk][3]) + bfh(a2l[kk][3]);
            racc[4 * kk + 2] += p0 * ya0 + p1 * yb0;
            racc[4 * kk + 3] += p0 * ya1 + p1 * yb1;
        }
    }

    // ---- block reduction: sum over g-lanes, then over m-warps ----
#pragma unroll
    for (int i = 0; i < 16; i++) {
        racc[i] += __shfl_xor_sync(~0u, racc[i], 4);
        racc[i] += __shfl_xor_sync(~0u, racc[i], 8);
        racc[i] += __shfl_xor_sync(~0u, racc[i], 16);
    }
    __syncthreads();   // all warps past last sqf read before redf reuse (also orders racc stores)
    if (lane < 4) {
#pragma unroll
        for (int i = 0; i < 16; i++) redf[(w * 4 + lane) * 16 + i] = racc[i];
    }
    __syncthreads();
    if (t < 128) {
        int col = t;
        int dl = col & 1;
        int tg = (col & 7) >> 1;
        int nt = (col & 63) >> 3;
        int jh2 = col >> 6;
        float v = 0.0f;
#pragma unroll
        for (int m2 = 0; m2 < 4; m2++)
            v += redf[((jh2 * 4 + m2) * 4 + tg) * 16 + nt * 2 + dl];
        g_part[sh][br * (BB * HD) + b * HD + col] = v;
    }
}

// ============ kernel 3: deterministic partial reduction (vectorized) ============
__global__ void k_reduce(float* __restrict__ out) {
    int i = blockIdx.x * 256 + threadIdx.x;  // 64 blocks x 256 thr x float4
    float4 a = ((const float4*)g_part[0])[i];
    float4 b = ((const float4*)g_part[1])[i];
    float4 c = ((const float4*)g_part[2])[i];
    float4 d = ((const float4*)g_part[3])[i];
    float4 s;
    s.x = (a.x + b.x) + (c.x + d.x);
    s.y = (a.y + b.y) + (c.y + d.y);
    s.z = (a.z + b.z) + (c.z + d.z);
    s.w = (a.w + b.w) + (c.w + d.w);
    ((float4*)out)[i] = s;
}

// ================= launcher ==============================================
extern "C" void kernel_launch(void* const* d_in, const int* in_sizes, int n_in,
                              void* d_out, int out_size) {
    const float* xl   = (const float*)d_in[0];
    const float* xn   = (const float*)d_in[1];
    const float* y    = (const float*)d_in[2];
    const float* uid  = (const float*)d_in[3];
    const float* osb  = (const float*)d_in[4];
    const float* zip  = (const float*)d_in[5];
    const float* w_ty = (const float*)d_in[6];
    const float* b_ty = (const float*)d_in[7];
    const float* a_ty = (const float*)d_in[8];
    const float* w_lx = (const float*)d_in[9];
    const float* b_lx = (const float*)d_in[10];
    const float* a_lx = (const float*)d_in[11];
    const float* w_nx = (const float*)d_in[12];
    const float* b_nx = (const float*)d_in[13];
    const float* a_nx = (const float*)d_in[14];
    const float* lw1  = (const float*)d_in[15];
    const float* lb1  = (const float*)d_in[16];
    const float* la1  = (const float*)d_in[17];
    const float* lw2  = (const float*)d_in[18];
    const float* lb2  = (const float*)d_in[19];
    const float* nw1  = (const float*)d_in[20];
    const float* nb1  = (const float*)d_in[21];
    const float* na1  = (const float*)d_in[22];
    const float* nw2  = (const float*)d_in[23];
    const float* nb2  = (const float*)d_in[24];
    float* out = (float*)d_out;

    cudaFuncSetAttribute(k_main, cudaFuncAttributeMaxDynamicSharedMemorySize, SMEM_TOTAL);

    k_pre<<<dim3(BB, 2, 2), 256>>>(y, w_ty, b_ty, a_ty, uid, osb, zip,
                                   lw1, lb1, nw1, nb1, w_lx, w_nx);
    k_main<<<dim3(BB, 2, 4), 256, SMEM_TOTAL>>>(xl, xn,
                                                b_lx, a_lx, b_nx, a_nx,
                                                la1, na1, lw2, lb2, nw2, nb2);
    k_reduce<<<(2 * BB * HD) / 1024, 256>>>(out);
}

// round 16
// speedup vs baseline: 1.1952x; 1.1952x over previous
#include <cuda_runtime.h>
#include <cuda_fp16.h>
#include <cstdint>

#define BB 256
#define SS 1024
#define DD 64
#define HD 128
#define FF 40

// ---------------- smem layout (byte offsets) ----------------
// fp16 rows of 64 K-elements padded to 144 bytes (conflict-free frag loads)
#define WSTR 144
#define OFF_WHI 0          // 128 rows x 144  (wx hi)
#define OFF_EHI 18432      // 80 rows x 144   (Weff^T hi)
#define OFF_XHI 29952      // 64 rows x 144   (x hi)
#define OFF_XLO 39168      // 64 rows x 144   (x residual)
#define OFF_BX  48384      // 128 f32
#define OFF_C   48896      // 80 f32
#define OFF_W2  49216      // 40 f32
#define OFF_SQ  49408      // 128 f32
#define OFF_RED 49920      // 2048 B
#define SMEM_TOTAL 53248

// ---------------- helpers ----------------
__device__ __forceinline__ float prelu_f(float x, float a) { return x >= 0.0f ? x : a * x; }

__device__ __forceinline__ uint32_t smem_u32(const void* p) {
    uint32_t a;
    asm("{ .reg .u64 t; cvta.to.shared.u64 t, %1; cvt.u32.u64 %0, t; }" : "=r"(a) : "l"(p));
    return a;
}

// pack two f32 -> f16x2 (f0 -> low, f1 -> high)
__device__ __forceinline__ uint32_t pkhf(float f0, float f1) {
    uint32_t r;
    asm("cvt.rn.f16x2.f32 %0, %1, %2;" : "=r"(r) : "f"(f1), "f"(f0));
    return r;
}
__device__ __forceinline__ float2 upkh(uint32_t u) {
    __half2 h = *reinterpret_cast<__half2*>(&u);
    return __half22float2(h);
}
// split pair into f16 hi + f16 residual lo
__device__ __forceinline__ void split2h(float f0, float f1, uint32_t& hi, uint32_t& lo) {
    hi = pkhf(f0, f1);
    float2 hf = upkh(hi);
    lo = pkhf(f0 - hf.x, f1 - hf.y);
}

__device__ __forceinline__ void mma_f16(float* c, const uint32_t* a, const uint32_t* b) {
    asm volatile(
        "mma.sync.aligned.m16n8k16.row.col.f32.f16.f16.f32 "
        "{%0,%1,%2,%3}, {%4,%5,%6,%7}, {%8,%9}, {%0,%1,%2,%3};"
        : "+f"(c[0]), "+f"(c[1]), "+f"(c[2]), "+f"(c[3])
        : "r"(a[0]), "r"(a[1]), "r"(a[2]), "r"(a[3]), "r"(b[0]), "r"(b[1]));
}

__device__ __forceinline__ void ldsm4(uint32_t* r, uint32_t addr) {
    asm volatile("ldmatrix.sync.aligned.m8n8.x4.shared.b16 {%0,%1,%2,%3}, [%4];"
        : "=r"(r[0]), "=r"(r[1]), "=r"(r[2]), "=r"(r[3]) : "r"(addr));
}
__device__ __forceinline__ void ldsm2(uint32_t* r, uint32_t addr) {
    asm volatile("ldmatrix.sync.aligned.m8n8.x2.shared.b16 {%0,%1}, [%2];"
        : "=r"(r[0]), "=r"(r[1]) : "r"(addr));
}

// ---------------- device scratch ----------------
// pre-split transposed fp16 weights (written by k_pre, copied by k_main)
__device__ float4 g_wxs[2][1024];        // [br][128 rows x 64 d fp16 hi]
__device__ float4 g_weffs[2 * BB][640];  // [(br*BB+b)][80 rows x 64 d fp16 hi]
__device__ float g_c[2 * BB * 2 * FF];
__device__ float g_part[4][2 * BB * HD];

// ============ kernel 1: y_trans + fp16 W_eff + c, one (b, br) per block ============
__global__ __launch_bounds__(256) void k_pre(
    const float* __restrict__ y, const float* __restrict__ w_ty,
    const float* __restrict__ b_ty, const float* __restrict__ a_ty,
    const float* __restrict__ uid, const float* __restrict__ osb,
    const float* __restrict__ zip,
    const float* __restrict__ lw1, const float* __restrict__ lb1,
    const float* __restrict__ nw1, const float* __restrict__ nb1,
    const float* __restrict__ wlx, const float* __restrict__ wnx) {
    int b = blockIdx.x, br = blockIdx.y, t = threadIdx.x;
    const float* w1 = br ? nw1 : lw1;
    const float* b1 = br ? nb1 : lb1;
    __shared__ float ys[DD], yt[HD], side[56], red[4];
    if (t < DD) ys[t] = y[b * DD + t];
    else if (t >= 64 && t < 120) {
        int k = t - 64;
        side[k] = (k < 32) ? uid[b * 32 + k]
                : (k < 40) ? osb[b * 8 + (k - 32)]
                           : zip[b * 16 + (k - 40)];
    }
    __syncthreads();
    float tv = 0.0f;
    if (t < HD) {
        float acc = b_ty[t];
#pragma unroll
        for (int d = 0; d < DD; d++) acc = fmaf(ys[d], w_ty[d * HD + t], acc);
        tv = prelu_f(acc, a_ty[0]);
        float sq = tv * tv;
#pragma unroll
        for (int off = 16; off; off >>= 1) sq += __shfl_xor_sync(~0u, sq, off);
        if ((t & 31) == 0) red[t >> 5] = sq;
    }
    __syncthreads();
    if (t < HD) {
        float s = red[0] + red[1] + red[2] + red[3];
        yt[t] = tv * (1.0f / fmaxf(sqrtf(s), 1e-12f));
    }
    __syncthreads();

    // W_eff both heads: fp16 hi, [f][d] transposed, coalesced stores
    {
        __half* eh = (__half*)g_weffs[br * BB + b];
        for (int i = t; i < 80 * 64; i += 256) {
            int row = i >> 6, d = i & 63;          // row = h*40+f
            int h = row / 40, f = row - h * 40;
            float v = w1[d * FF + f] + w1[(128 + d) * FF + f]
                    + yt[h * DD + d] * w1[(64 + d) * FF + f];
            eh[i] = __float2half(v);
        }
    }
    // c vector (both heads: t<80)
    if (t < 80) {
        int h = t / FF, f = t - h * FF;
        float acc = b1[f];
#pragma unroll 8
        for (int d = 0; d < DD; d++)
            acc += yt[h * DD + d] * (w1[(192 + d) * FF + f] - w1[(128 + d) * FF + f]);
#pragma unroll 8
        for (int k = 0; k < 56; k++) acc += side[k] * w1[(256 + k) * FF + f];
        g_c[(((size_t)br * BB + b) * 2 + h) * FF + f] = acc;
    }
    // wx split (once per branch): fp16 hi, [j][d] transposed
    if (b == 0) {
        const float* wx = br ? wnx : wlx;
        __half* wh = (__half*)g_wxs[br];
        for (int i = t; i < DD * HD; i += 256) {
            int j = i >> 6, d = i & 63;
            wh[i] = __float2half(wx[d * HD + j]);
        }
    }
}

// ============ kernel 2: main fp16 mma.sync kernel (copy-only setup; 2 barriers/tile) ============
__global__ __launch_bounds__(256, 2) void k_main(
    const float* __restrict__ xl, const float* __restrict__ xn_g,
    const float* __restrict__ blx, const float* __restrict__ alx,
    const float* __restrict__ bnx, const float* __restrict__ anx,
    const float* __restrict__ la1, const float* __restrict__ na1,
    const float* __restrict__ lw2, const float* __restrict__ lb2,
    const float* __restrict__ nw2, const float* __restrict__ nb2) {
    extern __shared__ char sm[];
    const uint32_t sb = smem_u32(sm);
    const int b = blockIdx.x, br = blockIdx.y, sh = blockIdx.z;
    const int t = threadIdx.x;
    const int w = t >> 5, lane = t & 31;
    const int mw = w & 3, jh = w >> 2;   // m-warp (rows mw*16..), n-half / head
    const int g = lane >> 2, tig = lane & 3;

    const float* xg = br ? xn_g : xl;
    const float* bx = br ? bnx : blx;
    const float ax = br ? anx[0] : alx[0];
    const float a1 = br ? na1[0] : la1[0];
    const float* w2g = br ? nw2 : lw2;
    const float b2 = br ? nb2[0] : lb2[0];

    float* bxs  = (float*)(sm + OFF_BX);
    float* c_s  = (float*)(sm + OFF_C);
    float* w2_s = (float*)(sm + OFF_W2);
    float* sqf  = (float*)(sm + OFF_SQ);
    float* redf = (float*)(sm + OFF_RED);

    // per-lane ldmatrix address components
    const uint32_t a_off = (uint32_t)(lane & 15) * WSTR + (uint32_t)(lane >> 4) * 16;
    const uint32_t b_off = (uint32_t)((lane >> 4) * 8 + (lane & 7)) * WSTR
                         + (uint32_t)((lane >> 3) & 1) * 16;
    const uint32_t b2_off = (uint32_t)(lane & 7) * WSTR + (uint32_t)((lane >> 3) & 1) * 16;

    // ---- setup: straight float4 copies of pre-split weights ----
    {
        const float4* swhi = g_wxs[br];
#pragma unroll
        for (int k = 0; k < 4; k++) {
            int i = t + k * 256;            // 1024 float4 = 128 rows x 8
            int row = i >> 3, q = i & 7;
            *(float4*)(sm + OFF_WHI + row * WSTR + q * 16) = swhi[i];
        }
        const float4* sehi = g_weffs[br * BB + b];
        for (int i = t; i < 640; i += 256) {  // 80 rows x 8
            int row = i >> 3, q = i & 7;
            *(float4*)(sm + OFF_EHI + row * WSTR + q * 16) = sehi[i];
        }
        const float* csrc = g_c + ((size_t)br * BB + b) * 2 * FF;
        if (t < 128) bxs[t] = bx[t];
        else if (t < 208) c_s[t - 128] = csrc[t - 128];
        else if (t < 248) w2_s[t - 208] = w2g[t - 208];
    }

    float racc[16];
#pragma unroll
    for (int i = 0; i < 16; i++) racc[i] = 0.0f;

    // prefetch tile 0
    const float4* xbase = (const float4*)xg + (size_t)(b * SS + sh * 256) * (DD / 4);
    float4 pf[4];
#pragma unroll
    for (int i = 0; i < 4; i++) pf[i] = xbase[t + i * 256];

    __syncthreads();

    for (int tile = 0; tile < 4; ++tile) {
        // ---- store prefetched x tile [64][64] -> split hi/lo fp16 smem ----
#pragma unroll
        for (int i = 0; i < 4; i++) {
            int idx = t + i * 256;          // 1024 float4
            int r = idx >> 4, kq = idx & 15;
            float4 v = pf[i];
            uint32_t h01, l01, h23, l23;
            split2h(v.x, v.y, h01, l01);
            split2h(v.z, v.w, h23, l23);
            *(uint2*)(sm + OFF_XHI + r * WSTR + kq * 8) = make_uint2(h01, h23);
            *(uint2*)(sm + OFF_XLO + r * WSTR + kq * 8) = make_uint2(l01, l23);
        }
        __syncthreads();   // barrier 1: X tile visible

        // prefetch next tile (LDG latency overlaps stage-1 MMAs)
        if (tile < 3) {
            const float4* xp = xbase + (tile + 1) * 1024;
#pragma unroll
            for (int i = 0; i < 4; i++) pf[i] = xp[t + i * 256];
        }

        // ---- stage 1: t1 = x @ wx (64x128, K=64), 2-term fp16 ----
        float acc[8][4];
#pragma unroll
        for (int nt = 0; nt < 8; nt++)
#pragma unroll
            for (int i = 0; i < 4; i++) acc[nt][i] = 0.0f;

#pragma unroll
        for (int kk = 0; kk < 4; kk++) {
            uint32_t aH[4], aL[4];
            uint32_t abase = sb + OFF_XHI + (uint32_t)(mw * 16) * WSTR + kk * 32 + a_off;
            ldsm4(aH, abase);
            ldsm4(aL, abase + (OFF_XLO - OFF_XHI));
#pragma unroll
            for (int np = 0; np < 4; np++) {
                uint32_t bH[4];
                uint32_t bbase = sb + OFF_WHI + (uint32_t)(jh * 64 + np * 16) * WSTR + kk * 32 + b_off;
                ldsm4(bH, bbase);
                mma_f16(acc[2 * np], aH, bH);
                mma_f16(acc[2 * np], aL, bH);
                mma_f16(acc[2 * np + 1], aH, bH + 2);
                mma_f16(acc[2 * np + 1], aL, bH + 2);
            }
        }

        // ---- epilogue 1: bias + prelu + l2norm (in registers, acc reused) ----
        float s0r = 0.0f, s1r = 0.0f;
#pragma unroll
        for (int nt = 0; nt < 8; nt++) {
            int c0 = jh * 64 + nt * 8 + 2 * tig;
            float b0v = bxs[c0], b1v = bxs[c0 + 1];
            float t0 = prelu_f(acc[nt][0] + b0v, ax);
            float t1 = prelu_f(acc[nt][1] + b1v, ax);
            float t2 = prelu_f(acc[nt][2] + b0v, ax);
            float t3 = prelu_f(acc[nt][3] + b1v, ax);
            acc[nt][0] = t0; acc[nt][1] = t1; acc[nt][2] = t2; acc[nt][3] = t3;
            s0r += t0 * t0 + t1 * t1;
            s1r += t2 * t2 + t3 * t3;
        }
        s0r += __shfl_xor_sync(~0u, s0r, 1); s0r += __shfl_xor_sync(~0u, s0r, 2);
        s1r += __shfl_xor_sync(~0u, s1r, 1); s1r += __shfl_xor_sync(~0u, s1r, 2);
        int row0 = mw * 16 + g;
        if (tig == 0) {
            sqf[jh * 64 + row0] = s0r;
            sqf[jh * 64 + row0 + 8] = s1r;
        }
        __syncthreads();   // barrier 2: row sumsq halves visible
        float inv0 = 1.0f / fmaxf(sqrtf(sqf[row0] + sqf[64 + row0]), 1e-12f);
        float inv1 = 1.0f / fmaxf(sqrtf(sqf[row0 + 8] + sqf[64 + row0 + 8]), 1e-12f);

        // normalize + build stage-2 A fragments (register resident)
        uint32_t a2h[4][4], a2l[4][4];
#pragma unroll
        for (int kk = 0; kk < 4; kk++) {
            split2h(acc[2 * kk][0] * inv0,     acc[2 * kk][1] * inv0,     a2h[kk][0], a2l[kk][0]);
            split2h(acc[2 * kk][2] * inv1,     acc[2 * kk][3] * inv1,     a2h[kk][1], a2l[kk][1]);
            split2h(acc[2 * kk + 1][0] * inv0, acc[2 * kk + 1][1] * inv0, a2h[kk][2], a2l[kk][2]);
            split2h(acc[2 * kk + 1][2] * inv1, acc[2 * kk + 1][3] * inv1, a2h[kk][3], a2l[kk][3]);
        }

        // ---- stage 2: h1 = xn_h @ Weff_h (64x40, K=64), 2-term fp16 ----
        float acc2[5][4];
#pragma unroll
        for (int nt = 0; nt < 5; nt++)
#pragma unroll
            for (int i = 0; i < 4; i++) acc2[nt][i] = 0.0f;
#pragma unroll
        for (int kk = 0; kk < 4; kk++) {
#pragma unroll
            for (int np = 0; np < 2; np++) {
                uint32_t bH[4];
                uint32_t bbase = sb + OFF_EHI + (uint32_t)(jh * 40 + np * 16) * WSTR + kk * 32 + b_off;
                ldsm4(bH, bbase);
                mma_f16(acc2[2 * np], a2h[kk], bH);
                mma_f16(acc2[2 * np], a2l[kk], bH);
                mma_f16(acc2[2 * np + 1], a2h[kk], bH + 2);
                mma_f16(acc2[2 * np + 1], a2l[kk], bH + 2);
            }
            {
                uint32_t bH[2];
                uint32_t bbase = sb + OFF_EHI + (uint32_t)(jh * 40 + 32) * WSTR + kk * 32 + b2_off;
                ldsm2(bH, bbase);
                mma_f16(acc2[4], a2h[kk], bH);
                mma_f16(acc2[4], a2l[kk], bH);
            }
        }

        // ---- epilogue 2: p = b2 + sum_f prelu(h1 + c) * w2 ----
        float p0 = 0.0f, p1 = 0.0f;
#pragma unroll
        for (int nt = 0; nt < 5; nt++) {
            int f0 = nt * 8 + 2 * tig;
            float c0v = c_s[jh * 40 + f0], c1v = c_s[jh * 40 + f0 + 1];
            float w0v = w2_s[f0], w1v = w2_s[f0 + 1];
            p0 += prelu_f(acc2[nt][0] + c0v, a1) * w0v + prelu_f(acc2[nt][1] + c1v, a1) * w1v;
            p1 += prelu_f(acc2[nt][2] + c0v, a1) * w0v + prelu_f(acc2[nt][3] + c1v, a1) * w1v;
        }
        p0 += __shfl_xor_sync(~0u, p0, 1); p0 += __shfl_xor_sync(~0u, p0, 2);
        p1 += __shfl_xor_sync(~0u, p1, 1); p1 += __shfl_xor_sync(~0u, p1, 2);
        p0 += b2; p1 += b2;

        // ---- epilogue 3: racc[col] += p0*xn[row g][col] + p1*xn[row g+8][col] ----
        // (register-only; no 3rd barrier needed — X/sq writers are gated behind
        //  next tile's barrier 1.)
#pragma unroll
        for (int kk = 0; kk < 4; kk++) {
            float2 xh0 = upkh(a2h[kk][0]), xl0 = upkh(a2l[kk][0]);
            float2 xh1 = upkh(a2h[kk][1]), xl1 = upkh(a2l[kk][1]);
            racc[4 * kk + 0] += p0 * (xh0.x + xl0.x) + p1 * (xh1.x + xl1.x);
            racc[4 * kk + 1] += p0 * (xh0.y + xl0.y) + p1 * (xh1.y + xl1.y);
            float2 yh0 = upkh(a2h[kk][2]), yl0 = upkh(a2l[kk][2]);
            float2 yh1 = upkh(a2h[kk][3]), yl1 = upkh(a2l[kk][3]);
            racc[4 * kk + 2] += p0 * (yh0.x + yl0.x) + p1 * (yh1.x + yl1.x);
            racc[4 * kk + 3] += p0 * (yh0.y + yl0.y) + p1 * (yh1.y + yl1.y);
        }
    }

    // ---- block reduction: sum over g-lanes, then over m-warps ----
#pragma unroll
    for (int i = 0; i < 16; i++) {
        racc[i] += __shfl_xor_sync(~0u, racc[i], 4);
        racc[i] += __shfl_xor_sync(~0u, racc[i], 8);
        racc[i] += __shfl_xor_sync(~0u, racc[i], 16);
    }
    __syncthreads();   // all warps past last sqf read before redf writes
    if (lane < 4) {
#pragma unroll
        for (int i = 0; i < 16; i++) redf[(w * 4 + lane) * 16 + i] = racc[i];
    }
    __syncthreads();
    if (t < 128) {
        int col = t;
        int dl = col & 1;
        int tg = (col & 7) >> 1;
        int nt = (col & 63) >> 3;
        int jh2 = col >> 6;
        float v = 0.0f;
#pragma unroll
        for (int m2 = 0; m2 < 4; m2++)
            v += redf[((jh2 * 4 + m2) * 4 + tg) * 16 + nt * 2 + dl];
        g_part[sh][br * (BB * HD) + b * HD + col] = v;
    }
}

// ============ kernel 3: deterministic partial reduction (vectorized) ============
__global__ void k_reduce(float* __restrict__ out) {
    int i = blockIdx.x * 256 + threadIdx.x;  // 64 blocks x 256 thr x float4
    float4 a = ((const float4*)g_part[0])[i];
    float4 b = ((const float4*)g_part[1])[i];
    float4 c = ((const float4*)g_part[2])[i];
    float4 d = ((const float4*)g_part[3])[i];
    float4 s;
    s.x = (a.x + b.x) + (c.x + d.x);
    s.y = (a.y + b.y) + (c.y + d.y);
    s.z = (a.z + b.z) + (c.z + d.z);
    s.w = (a.w + b.w) + (c.w + d.w);
    ((float4*)out)[i] = s;
}

// ================= launcher ==============================================
extern "C" void kernel_launch(void* const* d_in, const int* in_sizes, int n_in,
                              void* d_out, int out_size) {
    const float* xl   = (const float*)d_in[0];
    const float* xn   = (const float*)d_in[1];
    const float* y    = (const float*)d_in[2];
    const float* uid  = (const float*)d_in[3];
    const float* osb  = (const float*)d_in[4];
    const float* zip  = (const float*)d_in[5];
    const float* w_ty = (const float*)d_in[6];
    const float* b_ty = (const float*)d_in[7];
    const float* a_ty = (const float*)d_in[8];
    const float* w_lx = (const float*)d_in[9];
    const float* b_lx = (const float*)d_in[10];
    const float* a_lx = (const float*)d_in[11];
    const float* w_nx = (const float*)d_in[12];
    const float* b_nx = (const float*)d_in[13];
    const float* a_nx = (const float*)d_in[14];
    const float* lw1  = (const float*)d_in[15];
    const float* lb1  = (const float*)d_in[16];
    const float* la1  = (const float*)d_in[17];
    const float* lw2  = (const float*)d_in[18];
    const float* lb2  = (const float*)d_in[19];
    const float* nw1  = (const float*)d_in[20];
    const float* nb1  = (const float*)d_in[21];
    const float* na1  = (const float*)d_in[22];
    const float* nw2  = (const float*)d_in[23];
    const float* nb2  = (const float*)d_in[24];
    float* out = (float*)d_out;

    cudaFuncSetAttribute(k_main, cudaFuncAttributeMaxDynamicSharedMemorySize, SMEM_TOTAL);

    k_pre<<<dim3(BB, 2), 256>>>(y, w_ty, b_ty, a_ty, uid, osb, zip,
                                lw1, lb1, nw1, nb1, w_lx, w_nx);
    k_main<<<dim3(BB, 2, 4), 256, SMEM_TOTAL>>>(xl, xn,
                                                b_lx, a_lx, b_nx, a_nx,
                                                la1, na1, lw2, lb2, nw2, nb2);
    k_reduce<<<(2 * BB * HD) / 1024, 256>>>(out);
}